// round 3
// baseline (speedup 1.0000x reference)
#include <cuda_runtime.h>

#define BATCH 4
#define C 256
#define H 256
#define W 256
#define S 8
#define HP 32
#define WP 32
#define N 1024     // HP*WP tokens
#define KC 32      // key channels

typedef unsigned long long ull;

// ---- f32x2 packed-FMA helpers (sm_103a FFMA2 pipe, PTX-only) ----
__device__ __forceinline__ ull pack_dup(float x) {
    ull r; asm("mov.b64 %0, {%1, %1};" : "=l"(r) : "f"(x)); return r;
}
__device__ __forceinline__ float2 unpack2(ull v) {
    float2 r; asm("mov.b64 {%0, %1}, %2;" : "=f"(r.x), "=f"(r.y) : "l"(v)); return r;
}
#define FMA2(d, a, b) asm("fma.rn.f32x2 %0, %1, %2, %0;" : "+l"(d) : "l"(a), "l"(b))

// ---------------- device scratch (no allocs allowed) ----------------
__device__ float g_xf[BATCH * C * N];        // pooled features  [b][c][n]   4 MB
__device__ float g_q[BATCH * KC * N];        // q                [b][k][n]
__device__ float g_k[BATCH * KC * N];        // k                [b][k][n]
__device__ float g_v[BATCH * C * N];         // v                [b][c][n]   4 MB
__device__ float g_attn[BATCH * N * N];      // softmax probs    [b][n][m]  16 MB
__device__ float g_out[BATCH * C * N];       // attn output      [b][c][n]   4 MB

// ---------------- kernel 1: 8x8 avg pool ----------------
__global__ void avgpool_kernel(const float* __restrict__ f) {
    int idx = blockIdx.x * blockDim.x + threadIdx.x;   // over BATCH*C*N
    int n  = idx & (N - 1);
    int bc = idx >> 10;
    int wp = n & (WP - 1);
    int hp = n >> 5;
    const float* src = f + ((size_t)bc * H + (size_t)hp * S) * W + (size_t)wp * S;
    float s = 0.f;
#pragma unroll
    for (int r = 0; r < S; r++) {
        float4 a = *(const float4*)(src + (size_t)r * W);
        float4 b = *(const float4*)(src + (size_t)r * W + 4);
        s += a.x + a.y + a.z + a.w + b.x + b.y + b.z + b.w;
    }
    g_xf[idx] = s * (1.f / 64.f);
}

// ---------------- kernel 2: q/k/v 1x1 convs (f32x2) ----------------
// grid: (n_tiles=4, row_groups=10, batch=4), block 256
// each thread owns one token column n and 32 output rows as 16 f32x2 accs
__global__ void qkv_kernel(const float* __restrict__ qw, const float* __restrict__ qb,
                           const float* __restrict__ kw, const float* __restrict__ kb,
                           const float* __restrict__ vw, const float* __restrict__ vb) {
    __shared__ __align__(16) float wsh[C][32];   // transposed: wsh[c][r]
    __shared__ float bsh[32];
    int b = blockIdx.z;
    int g = blockIdx.y;
    int n = blockIdx.x * 256 + threadIdx.x;

    const float* wsrc;
    const float* bsrc;
    float* dst;
    int r0;
    if (g == 0)      { wsrc = qw; bsrc = qb; dst = g_q + (size_t)b * KC * N; r0 = 0; }
    else if (g == 1) { wsrc = kw; bsrc = kb; dst = g_k + (size_t)b * KC * N; r0 = 0; }
    else             { wsrc = vw; bsrc = vb; dst = g_v + (size_t)b * C * N;  r0 = (g - 2) * 32; }

    // load weights transposed: wsh[c][r] = w[r0+r][c]
    for (int i = threadIdx.x; i < 32 * C; i += 256) {
        int r = i & 31, c = i >> 5;
        wsh[c][r] = wsrc[(size_t)(r0 + r) * C + c];
    }
    if (threadIdx.x < 32) bsh[threadIdx.x] = bsrc[r0 + threadIdx.x];
    __syncthreads();

    const float* xf = g_xf + (size_t)b * C * N + n;
    ull acc[16];
#pragma unroll
    for (int p = 0; p < 16; p++) acc[p] = 0ULL;

#pragma unroll 4
    for (int c = 0; c < C; c++) {
        float x = __ldg(xf + (size_t)c * N);
        ull xd = pack_dup(x);
        const ulonglong2* wrow = (const ulonglong2*)&wsh[c][0];
#pragma unroll
        for (int q4 = 0; q4 < 4; q4++) {
            ulonglong2 wp2a = wrow[q4 * 2];
            ulonglong2 wp2b = wrow[q4 * 2 + 1];
            FMA2(acc[q4 * 4 + 0], xd, wp2a.x);
            FMA2(acc[q4 * 4 + 1], xd, wp2a.y);
            FMA2(acc[q4 * 4 + 2], xd, wp2b.x);
            FMA2(acc[q4 * 4 + 3], xd, wp2b.y);
        }
    }
#pragma unroll
    for (int p = 0; p < 16; p++) {
        float2 v = unpack2(acc[p]);
        dst[(size_t)(r0 + 2 * p) * N + n]     = v.x + bsh[2 * p];
        dst[(size_t)(r0 + 2 * p + 1) * N + n] = v.y + bsh[2 * p + 1];
    }
}

// ---------------- kernel 3: energy + softmax (f32x2) ----------------
#define QT 8   // query rows per block
__global__ void attn_prob_kernel() {
    int b  = blockIdx.y;
    int n0 = blockIdx.x * QT;
    int tid  = threadIdx.x;
    int lane = tid & 31, wid = tid >> 5;

    __shared__ float qsh[QT][KC];
    __shared__ float red_m[QT][8];
    __shared__ float red_s[QT][8];

    {
        int r = tid >> 5, k = tid & 31;
        qsh[r][k] = g_q[((size_t)b * KC + k) * N + (n0 + r)];
    }
    __syncthreads();

    // each thread owns m pairs: (2*tid, 2*tid+1) and (512+2*tid, 512+2*tid+1)
    ull e2[QT][2];
#pragma unroll
    for (int r = 0; r < QT; r++) { e2[r][0] = 0ULL; e2[r][1] = 0ULL; }

    const float* Kp = g_k + (size_t)b * KC * N;
#pragma unroll 4
    for (int k = 0; k < KC; k++) {
        ull kp0 = *(const ull*)(Kp + (size_t)k * N + 2 * tid);
        ull kp1 = *(const ull*)(Kp + (size_t)k * N + 512 + 2 * tid);
#pragma unroll
        for (int r = 0; r < QT; r++) {
            ull qd = pack_dup(qsh[r][k]);
            FMA2(e2[r][0], qd, kp0);
            FMA2(e2[r][1], qd, kp1);
        }
    }

    const float scale = 0.17677669529663687f;   // 32^-0.5
    float ev[QT][4];
#pragma unroll
    for (int r = 0; r < QT; r++) {
        float2 u0 = unpack2(e2[r][0]);
        float2 u1 = unpack2(e2[r][1]);
        ev[r][0] = u0.x * scale; ev[r][1] = u0.y * scale;
        ev[r][2] = u1.x * scale; ev[r][3] = u1.y * scale;
        float lm = fmaxf(fmaxf(ev[r][0], ev[r][1]), fmaxf(ev[r][2], ev[r][3]));
#pragma unroll
        for (int o = 16; o > 0; o >>= 1) lm = fmaxf(lm, __shfl_xor_sync(0xFFFFFFFFu, lm, o));
        if (lane == 0) red_m[r][wid] = lm;
    }
    __syncthreads();

#pragma unroll
    for (int r = 0; r < QT; r++) {
        float m2 = red_m[r][0];
#pragma unroll
        for (int w = 1; w < 8; w++) m2 = fmaxf(m2, red_m[r][w]);
        float ls = 0.f;
#pragma unroll
        for (int j = 0; j < 4; j++) { ev[r][j] = __expf(ev[r][j] - m2); ls += ev[r][j]; }
#pragma unroll
        for (int o = 16; o > 0; o >>= 1) ls += __shfl_xor_sync(0xFFFFFFFFu, ls, o);
        if (lane == 0) red_s[r][wid] = ls;
    }
    __syncthreads();

    float* P = g_attn + (size_t)b * N * N;
#pragma unroll
    for (int r = 0; r < QT; r++) {
        float s2 = red_s[r][0];
#pragma unroll
        for (int w = 1; w < 8; w++) s2 += red_s[r][w];
        float inv = 1.f / s2;
        float2 o0; o0.x = ev[r][0] * inv; o0.y = ev[r][1] * inv;
        float2 o1; o1.x = ev[r][2] * inv; o1.y = ev[r][3] * inv;
        *(float2*)(P + (size_t)(n0 + r) * N + 2 * tid)       = o0;
        *(float2*)(P + (size_t)(n0 + r) * N + 512 + 2 * tid) = o1;
    }
}

// ---------------- kernel 4: out = v @ attn^T (f32x2 tiled GEMM) ----------------
// out[b][c][n] = sum_m v[b][c][m] * attn[b][n][m]
// block tile: 64(c) x 64(n), k-tile 16(m), 128 threads, micro 4(c) x 8(n)
#define BM 64
#define BN 64
#define BK 16
__global__ void out_gemm_kernel() {
    int b  = blockIdx.z;
    int c0 = blockIdx.y * BM;
    int n0 = blockIdx.x * BN;
    __shared__ __align__(16) float As[BK][BM];  // As[m][c]
    __shared__ __align__(16) float Bs[BK][BN];  // Bs[m][n]

    int tid = threadIdx.x;            // 0..127
    int tx = tid & 7;                 // n dir: 8 threads x 8 cols
    int ty = tid >> 3;                // c dir: 16 threads x 4 rows
    const float* V = g_v    + (size_t)b * C * N;
    const float* P = g_attn + (size_t)b * N * N;

    ull acc[4][4];
#pragma unroll
    for (int i = 0; i < 4; i++)
#pragma unroll
        for (int j = 0; j < 4; j++) acc[i][j] = 0ULL;

    int lc  = tid & 63;               // row within tile (0..63)
    int lm8 = (tid >> 6) << 3;        // m sub-offset {0, 8}

    for (int m0 = 0; m0 < N; m0 += BK) {
        float4 av0 = *(const float4*)(V + (size_t)(c0 + lc) * N + m0 + lm8);
        float4 av1 = *(const float4*)(V + (size_t)(c0 + lc) * N + m0 + lm8 + 4);
        float4 bv0 = *(const float4*)(P + (size_t)(n0 + lc) * N + m0 + lm8);
        float4 bv1 = *(const float4*)(P + (size_t)(n0 + lc) * N + m0 + lm8 + 4);
        __syncthreads();
        As[lm8 + 0][lc] = av0.x; As[lm8 + 1][lc] = av0.y;
        As[lm8 + 2][lc] = av0.z; As[lm8 + 3][lc] = av0.w;
        As[lm8 + 4][lc] = av1.x; As[lm8 + 5][lc] = av1.y;
        As[lm8 + 6][lc] = av1.z; As[lm8 + 7][lc] = av1.w;
        Bs[lm8 + 0][lc] = bv0.x; Bs[lm8 + 1][lc] = bv0.y;
        Bs[lm8 + 2][lc] = bv0.z; Bs[lm8 + 3][lc] = bv0.w;
        Bs[lm8 + 4][lc] = bv1.x; Bs[lm8 + 5][lc] = bv1.y;
        Bs[lm8 + 6][lc] = bv1.z; Bs[lm8 + 7][lc] = bv1.w;
        __syncthreads();
#pragma unroll
        for (int kk = 0; kk < BK; kk++) {
            float4 a = *(const float4*)&As[kk][ty * 4];
            ulonglong2 b0 = *(const ulonglong2*)&Bs[kk][tx * 8];
            ulonglong2 b1 = *(const ulonglong2*)&Bs[kk][tx * 8 + 4];
            ull a0 = pack_dup(a.x), a1 = pack_dup(a.y);
            ull a2 = pack_dup(a.z), a3 = pack_dup(a.w);
            FMA2(acc[0][0], a0, b0.x); FMA2(acc[0][1], a0, b0.y);
            FMA2(acc[0][2], a0, b1.x); FMA2(acc[0][3], a0, b1.y);
            FMA2(acc[1][0], a1, b0.x); FMA2(acc[1][1], a1, b0.y);
            FMA2(acc[1][2], a1, b1.x); FMA2(acc[1][3], a1, b1.y);
            FMA2(acc[2][0], a2, b0.x); FMA2(acc[2][1], a2, b0.y);
            FMA2(acc[2][2], a2, b1.x); FMA2(acc[2][3], a2, b1.y);
            FMA2(acc[3][0], a3, b0.x); FMA2(acc[3][1], a3, b0.y);
            FMA2(acc[3][2], a3, b1.x); FMA2(acc[3][3], a3, b1.y);
        }
    }

    float* O = g_out + (size_t)b * C * N;
#pragma unroll
    for (int i = 0; i < 4; i++) {
        float2 u0 = unpack2(acc[i][0]);
        float2 u1 = unpack2(acc[i][1]);
        float2 u2 = unpack2(acc[i][2]);
        float2 u3 = unpack2(acc[i][3]);
        float4 lo; lo.x = u0.x; lo.y = u0.y; lo.z = u1.x; lo.w = u1.y;
        float4 hi; hi.x = u2.x; hi.y = u2.y; hi.z = u3.x; hi.w = u3.y;
        *(float4*)(O + (size_t)(c0 + ty * 4 + i) * N + n0 + tx * 8)     = lo;
        *(float4*)(O + (size_t)(c0 + ty * 4 + i) * N + n0 + tx * 8 + 4) = hi;
    }
}

// ---------------- kernel 5: nearest 8x upsample + residual ----------------
__global__ void upsample_add_kernel(const float* __restrict__ f, float* __restrict__ out) {
    size_t idx = (size_t)blockIdx.x * blockDim.x + threadIdx.x;  // over B*C*H*W/4
    int w4 = (int)(idx & 63);            // W/4 = 64
    int h  = (int)((idx >> 6) & 255);
    size_t bc = idx >> 14;
    int hp = h >> 3;
    int wp = w4 >> 1;                    // (w4*4)/8
    float s = g_out[bc * N + (size_t)hp * WP + wp];
    float4 a = ((const float4*)f)[idx];
    a.x += s; a.y += s; a.z += s; a.w += s;
    ((float4*)out)[idx] = a;
}

// ---------------- launch ----------------
extern "C" void kernel_launch(void* const* d_in, const int* in_sizes, int n_in,
                              void* d_out, int out_size) {
    const float* f  = (const float*)d_in[0];
    const float* qw = (const float*)d_in[1];
    const float* qb = (const float*)d_in[2];
    const float* kw = (const float*)d_in[3];
    const float* kb = (const float*)d_in[4];
    const float* vw = (const float*)d_in[5];
    const float* vb = (const float*)d_in[6];
    float* out = (float*)d_out;

    avgpool_kernel<<<(BATCH * C * N) / 256, 256>>>(f);
    qkv_kernel<<<dim3(4, 10, BATCH), 256>>>(qw, qb, kw, kb, vw, vb);
    attn_prob_kernel<<<dim3(N / QT, BATCH), 256>>>();
    out_gemm_kernel<<<dim3(N / BN, C / BM, BATCH), 128>>>();
    upsample_add_kernel<<<(BATCH * C * H * (W / 4)) / 256, 256>>>(f, out);
}

// round 4
// speedup vs baseline: 1.8071x; 1.8071x over previous
#include <cuda_runtime.h>

#define BATCH 4
#define C 256
#define H 256
#define W 256
#define S 8
#define HP 32
#define WP 32
#define N 1024     // HP*WP tokens
#define KC 32      // key channels

typedef unsigned int uint;

// ---------------- device scratch (no allocs allowed) ----------------
__device__ float g_xf[BATCH * C * N];        // pooled features  [b][c][n]   4 MB
__device__ float g_q[BATCH * KC * N];        // q                [b][k][n]
__device__ float g_k[BATCH * KC * N];        // k                [b][k][n]
__device__ float g_v[BATCH * C * N];         // v (tf32-rounded) [b][c][n]   4 MB
__device__ float g_attn[BATCH * N * N];      // probs (tf32-rnd) [b][n][m]  16 MB
__device__ float g_out[BATCH * C * N];       // attn output      [b][c][n]   4 MB

__device__ __forceinline__ float to_tf32(float x) {
    float r; asm("cvt.rna.tf32.f32 %0, %1;" : "=f"(r) : "f"(x)); return r;
}

__device__ __forceinline__ void mma_tf32(float* d, const uint* a, const uint* b) {
    asm volatile(
        "mma.sync.aligned.m16n8k8.row.col.f32.tf32.tf32.f32 "
        "{%0,%1,%2,%3}, {%4,%5,%6,%7}, {%8,%9}, {%0,%1,%2,%3};"
        : "+f"(d[0]), "+f"(d[1]), "+f"(d[2]), "+f"(d[3])
        : "r"(a[0]), "r"(a[1]), "r"(a[2]), "r"(a[3]), "r"(b[0]), "r"(b[1]));
}

// ---------------- kernel 1: 8x8 avg pool ----------------
__global__ void avgpool_kernel(const float* __restrict__ f) {
    int idx = blockIdx.x * blockDim.x + threadIdx.x;   // over BATCH*C*N
    int n  = idx & (N - 1);
    int bc = idx >> 10;
    int wp = n & (WP - 1);
    int hp = n >> 5;
    const float* src = f + ((size_t)bc * H + (size_t)hp * S) * W + (size_t)wp * S;
    float s = 0.f;
#pragma unroll
    for (int r = 0; r < S; r++) {
        float4 a = *(const float4*)(src + (size_t)r * W);
        float4 b = *(const float4*)(src + (size_t)r * W + 4);
        s += a.x + a.y + a.z + a.w + b.x + b.y + b.z + b.w;
    }
    g_xf[idx] = s * (1.f / 64.f);
}

// ---------------- kernel 2: q/k/v 1x1 convs (R1 scalar version) ----------------
// grid: (n_tiles=4, row_groups=20, batch=4), block 256
__global__ void qkv_kernel(const float* __restrict__ qw, const float* __restrict__ qb,
                           const float* __restrict__ kw, const float* __restrict__ kb,
                           const float* __restrict__ vw, const float* __restrict__ vb) {
    __shared__ float wsh[16][C];
    __shared__ float bsh[16];
    int b = blockIdx.z;
    int g = blockIdx.y;
    int n = blockIdx.x * 256 + threadIdx.x;

    const float* wsrc;
    const float* bsrc;
    float* dst;
    int r0;
    bool round_v;
    if (g < 2)      { wsrc = qw; bsrc = qb; dst = g_q + (size_t)b * KC * N; r0 = g * 16; round_v = false; }
    else if (g < 4) { wsrc = kw; bsrc = kb; dst = g_k + (size_t)b * KC * N; r0 = (g - 2) * 16; round_v = false; }
    else            { wsrc = vw; bsrc = vb; dst = g_v + (size_t)b * C * N;  r0 = (g - 4) * 16; round_v = true; }

    for (int i = threadIdx.x; i < 16 * C; i += 256)
        wsh[i >> 8][i & (C - 1)] = wsrc[(size_t)r0 * C + i];
    if (threadIdx.x < 16) bsh[threadIdx.x] = bsrc[r0 + threadIdx.x];
    __syncthreads();

    const float* xf = g_xf + (size_t)b * C * N + n;
    float acc[16];
#pragma unroll
    for (int r = 0; r < 16; r++) acc[r] = 0.f;

#pragma unroll 4
    for (int c = 0; c < C; c++) {
        float x = xf[(size_t)c * N];
#pragma unroll
        for (int r = 0; r < 16; r++) acc[r] = fmaf(wsh[r][c], x, acc[r]);
    }
#pragma unroll
    for (int r = 0; r < 16; r++) {
        float o = acc[r] + bsh[r];
        dst[(size_t)(r0 + r) * N + n] = round_v ? to_tf32(o) : o;
    }
}

// ---------------- kernel 3: energy + softmax (R1 version, tf32-rounded store) ----------------
#define QT 8   // query rows per block
__global__ void attn_prob_kernel() {
    int b  = blockIdx.y;
    int n0 = blockIdx.x * QT;
    int tid  = threadIdx.x;
    int lane = tid & 31, wid = tid >> 5;

    __shared__ float qsh[QT][KC];
    __shared__ float red_m[QT][8];
    __shared__ float red_s[QT][8];

    {
        int r = tid >> 5, k = tid & 31;
        qsh[r][k] = g_q[((size_t)b * KC + k) * N + (n0 + r)];
    }
    __syncthreads();

    float e[QT][4];
#pragma unroll
    for (int r = 0; r < QT; r++)
#pragma unroll
        for (int j = 0; j < 4; j++) e[r][j] = 0.f;

    const float* Kp = g_k + (size_t)b * KC * N;
#pragma unroll 4
    for (int k = 0; k < KC; k++) {
        float kv0 = Kp[(size_t)k * N + tid];
        float kv1 = Kp[(size_t)k * N + tid + 256];
        float kv2 = Kp[(size_t)k * N + tid + 512];
        float kv3 = Kp[(size_t)k * N + tid + 768];
#pragma unroll
        for (int r = 0; r < QT; r++) {
            float qv = qsh[r][k];
            e[r][0] = fmaf(qv, kv0, e[r][0]);
            e[r][1] = fmaf(qv, kv1, e[r][1]);
            e[r][2] = fmaf(qv, kv2, e[r][2]);
            e[r][3] = fmaf(qv, kv3, e[r][3]);
        }
    }

    const float scale = 0.17677669529663687f;   // 32^-0.5
#pragma unroll
    for (int r = 0; r < QT; r++) {
#pragma unroll
        for (int j = 0; j < 4; j++) e[r][j] *= scale;
        float lm = fmaxf(fmaxf(e[r][0], e[r][1]), fmaxf(e[r][2], e[r][3]));
#pragma unroll
        for (int o = 16; o > 0; o >>= 1) lm = fmaxf(lm, __shfl_xor_sync(0xFFFFFFFFu, lm, o));
        if (lane == 0) red_m[r][wid] = lm;
    }
    __syncthreads();

#pragma unroll
    for (int r = 0; r < QT; r++) {
        float m2 = red_m[r][0];
#pragma unroll
        for (int w = 1; w < 8; w++) m2 = fmaxf(m2, red_m[r][w]);
        float ls = 0.f;
#pragma unroll
        for (int j = 0; j < 4; j++) { e[r][j] = __expf(e[r][j] - m2); ls += e[r][j]; }
#pragma unroll
        for (int o = 16; o > 0; o >>= 1) ls += __shfl_xor_sync(0xFFFFFFFFu, ls, o);
        if (lane == 0) red_s[r][wid] = ls;
    }
    __syncthreads();

    float* P = g_attn + (size_t)b * N * N;
#pragma unroll
    for (int r = 0; r < QT; r++) {
        float s2 = red_s[r][0];
#pragma unroll
        for (int w = 1; w < 8; w++) s2 += red_s[r][w];
        float inv = 1.f / s2;
#pragma unroll
        for (int j = 0; j < 4; j++)
            P[(size_t)(n0 + r) * N + tid + j * 256] = to_tf32(e[r][j] * inv);
    }
}

// ---------------- kernel 4: out = v @ attn^T via tf32 HMMA ----------------
// out[b][c][n] = sum_m v[b][c][m] * attn[b][n][m]
// A = V rows (row-major over m), B = attn rows (col-major over m == row-major P) -> row.col mma fits both.
// block: 128 thr = 4 warps (2c x 2n), block tile 64(c) x 64(n), warp tile 32x32 (2x4 atoms), k-chunk 32.
#define GBM 64
#define GBN 64
#define GBK 32
#define LDP 36   // smem row stride (words): conflict-free fragment loads, 16B-aligned rows
__global__ void out_gemm_kernel() {
    int b  = blockIdx.z;
    int c0 = blockIdx.y * GBM;
    int n0 = blockIdx.x * GBN;
    __shared__ __align__(16) uint Vs[GBM * LDP];
    __shared__ __align__(16) uint Ps[GBN * LDP];

    int tid  = threadIdx.x;      // 0..127
    int lane = tid & 31, wid = tid >> 5;
    int wm = (wid & 1) * 32;     // warp c offset
    int wn = (wid >> 1) * 32;    // warp n offset

    const uint* V = (const uint*)g_v    + (size_t)b * C * N;
    const uint* P = (const uint*)g_attn + (size_t)b * N * N;

    float acc[2][4][4];
#pragma unroll
    for (int am = 0; am < 2; am++)
#pragma unroll
        for (int an = 0; an < 4; an++)
#pragma unroll
            for (int j = 0; j < 4; j++) acc[am][an][j] = 0.f;

    int r4  = lane >> 2;         // 0..7
    int q4  = lane & 3;          // 0..3

    for (int m0 = 0; m0 < N; m0 += GBK) {
        __syncthreads();
#pragma unroll
        for (int i = 0; i < 4; i++) {
            int idx = tid + i * 128;       // 0..511
            int row = idx >> 3, f4 = (idx & 7) * 4;
            uint4 vv = *(const uint4*)(V + (size_t)(c0 + row) * N + m0 + f4);
            uint4 pv = *(const uint4*)(P + (size_t)(n0 + row) * N + m0 + f4);
            *(uint4*)(Vs + row * LDP + f4) = vv;
            *(uint4*)(Ps + row * LDP + f4) = pv;
        }
        __syncthreads();

#pragma unroll
        for (int k8 = 0; k8 < GBK; k8 += 8) {
            uint a[2][4], bb[4][2];
#pragma unroll
            for (int am = 0; am < 2; am++) {
                int base = (wm + am * 16 + r4) * LDP + k8 + q4;
                a[am][0] = Vs[base];
                a[am][1] = Vs[base + 8 * LDP];
                a[am][2] = Vs[base + 4];
                a[am][3] = Vs[base + 8 * LDP + 4];
            }
#pragma unroll
            for (int an = 0; an < 4; an++) {
                int base = (wn + an * 8 + r4) * LDP + k8 + q4;
                bb[an][0] = Ps[base];
                bb[an][1] = Ps[base + 4];
            }
#pragma unroll
            for (int am = 0; am < 2; am++)
#pragma unroll
                for (int an = 0; an < 4; an++)
                    mma_tf32(acc[am][an], a[am], bb[an]);
        }
    }

    float* O = g_out + (size_t)b * C * N;
    int cc = (lane & 3) * 2;
#pragma unroll
    for (int am = 0; am < 2; am++)
#pragma unroll
        for (int an = 0; an < 4; an++) {
            int crow = c0 + wm + am * 16 + r4;
            int ncol = n0 + wn + an * 8 + cc;
            float2 lo; lo.x = acc[am][an][0]; lo.y = acc[am][an][1];
            float2 hi; hi.x = acc[am][an][2]; hi.y = acc[am][an][3];
            *(float2*)(O + (size_t)crow * N + ncol)       = lo;
            *(float2*)(O + (size_t)(crow + 8) * N + ncol) = hi;
        }
}

// ---------------- kernel 5: nearest 8x upsample + residual ----------------
__global__ void upsample_add_kernel(const float* __restrict__ f, float* __restrict__ out) {
    size_t idx = (size_t)blockIdx.x * blockDim.x + threadIdx.x;  // over B*C*H*W/4
    int w4 = (int)(idx & 63);            // W/4 = 64
    int h  = (int)((idx >> 6) & 255);
    size_t bc = idx >> 14;
    int hp = h >> 3;
    int wp = w4 >> 1;                    // (w4*4)/8
    float s = g_out[bc * N + (size_t)hp * WP + wp];
    float4 a = ((const float4*)f)[idx];
    a.x += s; a.y += s; a.z += s; a.w += s;
    ((float4*)out)[idx] = a;
}

// ---------------- launch ----------------
extern "C" void kernel_launch(void* const* d_in, const int* in_sizes, int n_in,
                              void* d_out, int out_size) {
    const float* f  = (const float*)d_in[0];
    const float* qw = (const float*)d_in[1];
    const float* qb = (const float*)d_in[2];
    const float* kw = (const float*)d_in[3];
    const float* kb = (const float*)d_in[4];
    const float* vw = (const float*)d_in[5];
    const float* vb = (const float*)d_in[6];
    float* out = (float*)d_out;

    avgpool_kernel<<<(BATCH * C * N) / 256, 256>>>(f);
    qkv_kernel<<<dim3(4, 20, BATCH), 256>>>(qw, qb, kw, kb, vw, vb);
    attn_prob_kernel<<<dim3(N / QT, BATCH), 256>>>();
    out_gemm_kernel<<<dim3(N / GBN, C / GBM, BATCH), 128>>>();
    upsample_add_kernel<<<(BATCH * C * H * (W / 4)) / 256, 256>>>(f, out);
}

// round 5
// speedup vs baseline: 1.9234x; 1.0644x over previous
#include <cuda_runtime.h>

#define BATCH 4
#define C 256
#define H 256
#define W 256
#define S 8
#define HP 32
#define WP 32
#define N 1024     // HP*WP tokens
#define KC 32      // key channels

typedef unsigned int uint;

// ---------------- device scratch (no allocs allowed) ----------------
__device__ float g_xf[BATCH * C * N];        // pooled features  [b][c][n]   4 MB
__device__ float g_q[BATCH * KC * N];        // q                [b][k][n]
__device__ float g_k[BATCH * KC * N];        // k                [b][k][n]
__device__ float g_v[BATCH * C * N];         // v (tf32-rounded) [b][c][n]   4 MB
__device__ float g_attn[BATCH * N * N];      // probs (tf32-rnd) [b][n][m]  16 MB
__device__ float g_out[BATCH * C * N];       // attn output      [b][c][n]   4 MB

__device__ __forceinline__ float to_tf32(float x) {
    float r; asm("cvt.rna.tf32.f32 %0, %1;" : "=f"(r) : "f"(x)); return r;
}

__device__ __forceinline__ void mma_tf32(float* d, const uint* a, const uint* b) {
    asm volatile(
        "mma.sync.aligned.m16n8k8.row.col.f32.tf32.tf32.f32 "
        "{%0,%1,%2,%3}, {%4,%5,%6,%7}, {%8,%9}, {%0,%1,%2,%3};"
        : "+f"(d[0]), "+f"(d[1]), "+f"(d[2]), "+f"(d[3])
        : "r"(a[0]), "r"(a[1]), "r"(a[2]), "r"(a[3]), "r"(b[0]), "r"(b[1]));
}

__device__ __forceinline__ void cp16(uint smem_addr, const void* gptr) {
    asm volatile("cp.async.ca.shared.global [%0], [%1], 16;"
                 :: "r"(smem_addr), "l"(gptr));
}

// ---------------- kernel 1: 8x8 avg pool ----------------
__global__ void avgpool_kernel(const float* __restrict__ f) {
    int idx = blockIdx.x * blockDim.x + threadIdx.x;   // over BATCH*C*N
    int n  = idx & (N - 1);
    int bc = idx >> 10;
    int wp = n & (WP - 1);
    int hp = n >> 5;
    const float* src = f + ((size_t)bc * H + (size_t)hp * S) * W + (size_t)wp * S;
    float s = 0.f;
#pragma unroll
    for (int r = 0; r < S; r++) {
        float4 a = *(const float4*)(src + (size_t)r * W);
        float4 b = *(const float4*)(src + (size_t)r * W + 4);
        s += a.x + a.y + a.z + a.w + b.x + b.y + b.z + b.w;
    }
    g_xf[idx] = s * (1.f / 64.f);
}

// ---------------- kernel 2: q/k/v 1x1 convs ----------------
// grid: (n_tiles=4, row_groups=20, batch=4), block 256
__global__ void qkv_kernel(const float* __restrict__ qw, const float* __restrict__ qb,
                           const float* __restrict__ kw, const float* __restrict__ kb,
                           const float* __restrict__ vw, const float* __restrict__ vb) {
    __shared__ float wsh[16][C];
    __shared__ float bsh[16];
    int b = blockIdx.z;
    int g = blockIdx.y;
    int n = blockIdx.x * 256 + threadIdx.x;

    const float* wsrc;
    const float* bsrc;
    float* dst;
    int r0;
    bool round_v;
    if (g < 2)      { wsrc = qw; bsrc = qb; dst = g_q + (size_t)b * KC * N; r0 = g * 16; round_v = false; }
    else if (g < 4) { wsrc = kw; bsrc = kb; dst = g_k + (size_t)b * KC * N; r0 = (g - 2) * 16; round_v = false; }
    else            { wsrc = vw; bsrc = vb; dst = g_v + (size_t)b * C * N;  r0 = (g - 4) * 16; round_v = true; }

    for (int i = threadIdx.x; i < 16 * C; i += 256)
        wsh[i >> 8][i & (C - 1)] = wsrc[(size_t)r0 * C + i];
    if (threadIdx.x < 16) bsh[threadIdx.x] = bsrc[r0 + threadIdx.x];
    __syncthreads();

    const float* xf = g_xf + (size_t)b * C * N + n;
    float acc[16];
#pragma unroll
    for (int r = 0; r < 16; r++) acc[r] = 0.f;

#pragma unroll 4
    for (int c = 0; c < C; c++) {
        float x = xf[(size_t)c * N];
#pragma unroll
        for (int r = 0; r < 16; r++) acc[r] = fmaf(wsh[r][c], x, acc[r]);
    }
#pragma unroll
    for (int r = 0; r < 16; r++) {
        float o = acc[r] + bsh[r];
        dst[(size_t)(r0 + r) * N + n] = round_v ? to_tf32(o) : o;
    }
}

// ---------------- kernel 3: energy + softmax (tf32-rounded store) ----------------
#define QT 8   // query rows per block
__global__ void attn_prob_kernel() {
    int b  = blockIdx.y;
    int n0 = blockIdx.x * QT;
    int tid  = threadIdx.x;
    int lane = tid & 31, wid = tid >> 5;

    __shared__ float qsh[QT][KC];
    __shared__ float red_m[QT][8];
    __shared__ float red_s[QT][8];

    {
        int r = tid >> 5, k = tid & 31;
        qsh[r][k] = g_q[((size_t)b * KC + k) * N + (n0 + r)];
    }
    __syncthreads();

    float e[QT][4];
#pragma unroll
    for (int r = 0; r < QT; r++)
#pragma unroll
        for (int j = 0; j < 4; j++) e[r][j] = 0.f;

    const float* Kp = g_k + (size_t)b * KC * N;
#pragma unroll 4
    for (int k = 0; k < KC; k++) {
        float kv0 = Kp[(size_t)k * N + tid];
        float kv1 = Kp[(size_t)k * N + tid + 256];
        float kv2 = Kp[(size_t)k * N + tid + 512];
        float kv3 = Kp[(size_t)k * N + tid + 768];
#pragma unroll
        for (int r = 0; r < QT; r++) {
            float qv = qsh[r][k];
            e[r][0] = fmaf(qv, kv0, e[r][0]);
            e[r][1] = fmaf(qv, kv1, e[r][1]);
            e[r][2] = fmaf(qv, kv2, e[r][2]);
            e[r][3] = fmaf(qv, kv3, e[r][3]);
        }
    }

    const float scale = 0.17677669529663687f;   // 32^-0.5
#pragma unroll
    for (int r = 0; r < QT; r++) {
#pragma unroll
        for (int j = 0; j < 4; j++) e[r][j] *= scale;
        float lm = fmaxf(fmaxf(e[r][0], e[r][1]), fmaxf(e[r][2], e[r][3]));
#pragma unroll
        for (int o = 16; o > 0; o >>= 1) lm = fmaxf(lm, __shfl_xor_sync(0xFFFFFFFFu, lm, o));
        if (lane == 0) red_m[r][wid] = lm;
    }
    __syncthreads();

#pragma unroll
    for (int r = 0; r < QT; r++) {
        float m2 = red_m[r][0];
#pragma unroll
        for (int w = 1; w < 8; w++) m2 = fmaxf(m2, red_m[r][w]);
        float ls = 0.f;
#pragma unroll
        for (int j = 0; j < 4; j++) { e[r][j] = __expf(e[r][j] - m2); ls += e[r][j]; }
#pragma unroll
        for (int o = 16; o > 0; o >>= 1) ls += __shfl_xor_sync(0xFFFFFFFFu, ls, o);
        if (lane == 0) red_s[r][wid] = ls;
    }
    __syncthreads();

    float* P = g_attn + (size_t)b * N * N;
#pragma unroll
    for (int r = 0; r < QT; r++) {
        float s2 = red_s[r][0];
#pragma unroll
        for (int w = 1; w < 8; w++) s2 += red_s[r][w];
        float inv = 1.f / s2;
#pragma unroll
        for (int j = 0; j < 4; j++)
            P[(size_t)(n0 + r) * N + tid + j * 256] = to_tf32(e[r][j] * inv);
    }
}

// ---------------- kernel 4: out = v @ attn^T via tf32 HMMA + cp.async pipeline ----------------
// out[b][c][n] = sum_m v[b][c][m] * attn[b][n][m]
// block: 128 thr = 4 warps (2c x 2n), block tile 64(c) x 64(n), warp tile 32x32, k-chunk 32, 2-stage.
#define GBM 64
#define GBN 64
#define GBK 32
#define LDP 36   // smem row stride (words): bank = lane for fragment loads -> conflict-free
#define NCHUNK (N / GBK)
__global__ void out_gemm_kernel() {
    int b  = blockIdx.z;
    int c0 = blockIdx.y * GBM;
    int n0 = blockIdx.x * GBN;
    __shared__ __align__(16) uint Vs[2][GBM * LDP];
    __shared__ __align__(16) uint Ps[2][GBN * LDP];

    int tid  = threadIdx.x;      // 0..127
    int lane = tid & 31, wid = tid >> 5;
    int wm = (wid & 1) * 32;     // warp c offset
    int wn = (wid >> 1) * 32;    // warp n offset

    const uint* V = (const uint*)g_v    + (size_t)b * C * N;
    const uint* P = (const uint*)g_attn + (size_t)b * N * N;

    // per-thread copy slots: idx = tid + i*128 -> row = idx>>3 (0..63), f4 = (idx&7)*4
    int crow = tid >> 3;
    int cf4  = (tid & 7) * 4;

    float acc[2][4][4];
#pragma unroll
    for (int am = 0; am < 2; am++)
#pragma unroll
        for (int an = 0; an < 4; an++)
#pragma unroll
            for (int j = 0; j < 4; j++) acc[am][an][j] = 0.f;

    int r4  = lane >> 2;         // 0..7
    int q4  = lane & 3;          // 0..3

    // stage-0 prefetch
    {
#pragma unroll
        for (int i = 0; i < 4; i++) {
            int row = crow + i * 16;  // i*128 threads -> +16 rows
            cp16((uint)__cvta_generic_to_shared(&Vs[0][row * LDP + cf4]),
                 V + (size_t)(c0 + row) * N + cf4);
            cp16((uint)__cvta_generic_to_shared(&Ps[0][row * LDP + cf4]),
                 P + (size_t)(n0 + row) * N + cf4);
        }
        asm volatile("cp.async.commit_group;");
    }

    for (int ch = 0; ch < NCHUNK; ch++) {
        int s = ch & 1;
        if (ch + 1 < NCHUNK) {
            int m1 = (ch + 1) * GBK;
#pragma unroll
            for (int i = 0; i < 4; i++) {
                int row = crow + i * 16;
                cp16((uint)__cvta_generic_to_shared(&Vs[s ^ 1][row * LDP + cf4]),
                     V + (size_t)(c0 + row) * N + m1 + cf4);
                cp16((uint)__cvta_generic_to_shared(&Ps[s ^ 1][row * LDP + cf4]),
                     P + (size_t)(n0 + row) * N + m1 + cf4);
            }
            asm volatile("cp.async.commit_group;");
            asm volatile("cp.async.wait_group 1;");
        } else {
            asm volatile("cp.async.wait_group 0;");
        }
        __syncthreads();

        const uint* Vss = Vs[s];
        const uint* Pss = Ps[s];
#pragma unroll
        for (int k8 = 0; k8 < GBK; k8 += 8) {
            uint a[2][4], bb[4][2];
#pragma unroll
            for (int am = 0; am < 2; am++) {
                int base = (wm + am * 16 + r4) * LDP + k8 + q4;
                a[am][0] = Vss[base];
                a[am][1] = Vss[base + 8 * LDP];
                a[am][2] = Vss[base + 4];
                a[am][3] = Vss[base + 8 * LDP + 4];
            }
#pragma unroll
            for (int an = 0; an < 4; an++) {
                int base = (wn + an * 8 + r4) * LDP + k8 + q4;
                bb[an][0] = Pss[base];
                bb[an][1] = Pss[base + 4];
            }
#pragma unroll
            for (int am = 0; am < 2; am++)
#pragma unroll
                for (int an = 0; an < 4; an++)
                    mma_tf32(acc[am][an], a[am], bb[an]);
        }
        __syncthreads();
    }

    float* O = g_out + (size_t)b * C * N;
    int cc = (lane & 3) * 2;
#pragma unroll
    for (int am = 0; am < 2; am++)
#pragma unroll
        for (int an = 0; an < 4; an++) {
            int cr = c0 + wm + am * 16 + r4;
            int ncol = n0 + wn + an * 8 + cc;
            float2 lo; lo.x = acc[am][an][0]; lo.y = acc[am][an][1];
            float2 hi; hi.x = acc[am][an][2]; hi.y = acc[am][an][3];
            *(float2*)(O + (size_t)cr * N + ncol)       = lo;
            *(float2*)(O + (size_t)(cr + 8) * N + ncol) = hi;
        }
}

// ---------------- kernel 5: nearest 8x upsample + residual ----------------
__global__ void upsample_add_kernel(const float* __restrict__ f, float* __restrict__ out) {
    size_t idx = (size_t)blockIdx.x * blockDim.x + threadIdx.x;  // over B*C*H*W/4
    int w4 = (int)(idx & 63);            // W/4 = 64
    int h  = (int)((idx >> 6) & 255);
    size_t bc = idx >> 14;
    int hp = h >> 3;
    int wp = w4 >> 1;                    // (w4*4)/8
    float s = g_out[bc * N + (size_t)hp * WP + wp];
    float4 a = ((const float4*)f)[idx];
    a.x += s; a.y += s; a.z += s; a.w += s;
    ((float4*)out)[idx] = a;
}

// ---------------- launch ----------------
extern "C" void kernel_launch(void* const* d_in, const int* in_sizes, int n_in,
                              void* d_out, int out_size) {
    const float* f  = (const float*)d_in[0];
    const float* qw = (const float*)d_in[1];
    const float* qb = (const float*)d_in[2];
    const float* kw = (const float*)d_in[3];
    const float* kb = (const float*)d_in[4];
    const float* vw = (const float*)d_in[5];
    const float* vb = (const float*)d_in[6];
    float* out = (float*)d_out;

    avgpool_kernel<<<(BATCH * C * N) / 256, 256>>>(f);
    qkv_kernel<<<dim3(4, 20, BATCH), 256>>>(qw, qb, kw, kb, vw, vb);
    attn_prob_kernel<<<dim3(N / QT, BATCH), 256>>>();
    out_gemm_kernel<<<dim3(N / GBN, C / GBM, BATCH), 128>>>();
    upsample_add_kernel<<<(BATCH * C * H * (W / 4)) / 256, 256>>>(f, out);
}